// round 10
// baseline (speedup 1.0000x reference)
#include <cuda_runtime.h>
#include <stdint.h>

// ---------------------------------------------------------------------------
// Graph-SAGE 3-hop, F=1.
// One-time: counting-sort edges into (dst-tile, src-tile) groups:
//   DT=12288 (82 dst tiles), ST=16384 (62 src tiles), 5084 groups.
// Per hop: zero g_neigh; hop kernel = persistent dst-tile blocks (2 replicas,
// grid 164): 48KB smem acc + 64KB smem src stage; per edge LDS + smem ATOMS;
// writeback = coalesced REDG (2M/hop, not 41M); then combine kernel.
// Packed edge = dst_local<<14 | src_local  (dst_local<12288, src_local<16384).
// ---------------------------------------------------------------------------

#define DT      12288
#define NDT     82                      // ceil(1e6/12288)
#define ST      16384
#define NST     62                      // ceil(1e6/16384)
#define NG      (NDT * NST)             // 5084
#define NGP     8192                    // pow2 >= NG (scan width)
#define GCAP    7936                    // mean 6442, std ~80 -> +18.7 sigma
#define CHUNK   32768                   // edges per binsort block
#define MAX_N   (NDT * DT)              // 1,007,616

__device__ uint32_t g_pairs[(size_t)NG * GCAP];   // ~161 MB scratch
__device__ int      g_cursor[NG];
__device__ float    g_neigh[MAX_N];
__device__ float    g_hA[MAX_N];
__device__ float    g_hB[MAX_N];
__device__ int      g_sink;

// --- init: cursor[g] = g*GCAP ----------------------------------------------
__global__ void init_cursor_kernel() {
    int g = blockIdx.x * blockDim.x + threadIdx.x;
    if (g < NG) g_cursor[g] = g * GCAP;
}

// --- spacer (launch-index alignment: ncu -s 5 lands on the hop kernel) -----
__global__ void spacer_kernel() {
    if (threadIdx.x == 0) g_sink = 1;
}

// --- binsort: smem counting sort of a 32K-edge chunk into 5084 groups ------
// dyn smem: cnt[NGP] | cur[NGP] | gbase[NGP] | buf[CHUNK]   (224 KB)
__global__ __launch_bounds__(512)
void binsort_kernel(const int* __restrict__ src,
                    const int* __restrict__ dst,
                    int ne) {
    extern __shared__ int sm[];
    int*      cnt   = sm;
    int*      cur   = sm + NGP;
    int*      gbase = sm + 2 * NGP;
    uint32_t* buf   = (uint32_t*)(sm + 3 * NGP);

    const int tid = threadIdx.x;
    const int lo = blockIdx.x * CHUNK;
    const int hi = min(ne, lo + CHUNK);

    #pragma unroll
    for (int k = 0; k < NGP / 512; k++) cnt[tid + 512 * k] = 0;
    __syncthreads();

    // Phase A: count groups (coalesced reads, spread smem atomics)
    for (int e = lo + tid; e < hi; e += 512) {
        int g = (dst[e] / DT) * NST + (src[e] >> 14);
        atomicAdd(&cnt[g], 1);
    }
    __syncthreads();

    // Phase B: Hillis-Steele inclusive scan over NGP (16 elems/thread)
    #pragma unroll
    for (int k = 0; k < NGP / 512; k++) cur[tid + 512 * k] = cnt[tid + 512 * k];
    __syncthreads();
    for (int off = 1; off < NGP; off <<= 1) {
        int a[NGP / 512];
        #pragma unroll
        for (int k = 0; k < NGP / 512; k++) {
            int i = tid + 512 * k;
            a[k] = (i >= off) ? cur[i - off] : 0;
        }
        __syncthreads();
        #pragma unroll
        for (int k = 0; k < NGP / 512; k++) cur[tid + 512 * k] += a[k];
        __syncthreads();
    }
    // exclusive start into cur; reserve global ranges
    {
        int s_[NGP / 512];
        #pragma unroll
        for (int k = 0; k < NGP / 512; k++) {
            int i = tid + 512 * k;
            s_[k] = cur[i] - cnt[i];
        }
        __syncthreads();
        #pragma unroll
        for (int k = 0; k < NGP / 512; k++) {
            int i = tid + 512 * k;
            cur[i]   = s_[k];
            gbase[i] = (i < NG && cnt[i]) ? atomicAdd(&g_cursor[i], cnt[i]) : 0;
        }
    }
    __syncthreads();

    // Phase C: scatter packed edges into smem buffer
    for (int e = lo + tid; e < hi; e += 512) {
        int d = dst[e], s = src[e];
        int dt_ = d / DT;
        int g = dt_ * NST + (s >> 14);
        int pos = atomicAdd(&cur[g], 1);
        buf[pos] = ((uint32_t)(d - dt_ * DT) << 14) | (uint32_t)(s & 16383);
    }
    __syncthreads();

    // Phase D: coalesced copy-out, one warp per group run (~6 words each)
    int warp = tid >> 5, lane = tid & 31;
    for (int g = warp; g < NG; g += 16) {
        int c = cnt[g];
        if (!c) continue;
        int sb = cur[g] - c;          // cur is now exclusive start + cnt
        int gb = gbase[g];
        for (int j = lane; j < c; j += 32)
            g_pairs[gb + j] = buf[sb + j];
    }
}

// --- zero the global neighbor accumulator ----------------------------------
__global__ void zero_kernel(int n4) {
    int i = blockIdx.x * blockDim.x + threadIdx.x;
    if (i < n4) ((float4*)g_neigh)[i] = make_float4(0.f, 0.f, 0.f, 0.f);
}

// --- hop: persistent dst-tile block (2 replicas), loops over src-tiles -----
__global__ __launch_bounds__(512)
void hop_kernel(const float* __restrict__ h, int n) {
    extern __shared__ float fsm[];
    float* acc   = fsm;          // DT floats (48 KB)
    float* stage = fsm + DT;     // ST floats (64 KB)

    const int bid  = blockIdx.x;
    const int dt_  = bid >> 1;
    const int rep  = bid & 1;
    const int tid  = threadIdx.x;
    const int dbase = dt_ * DT;

    for (int i = tid; i < DT; i += 512) acc[i] = 0.f;

    for (int st_ = rep; st_ < NST; st_ += 2) {
        const int sbase = st_ << 14;
        __syncthreads();   // prior-iter stage readers done; also orders acc zero
        // stage h[src tile] into smem
        if (sbase + ST <= n) {
            const float4* h4 = (const float4*)(h + sbase);
            for (int i = tid; i < ST / 4; i += 512)
                ((float4*)stage)[i] = h4[i];
        } else {
            for (int i = tid; i < ST; i += 512) {
                int node = sbase + i;
                stage[i] = (node < n) ? h[node] : 0.f;
            }
        }
        __syncthreads();

        const int g  = dt_ * NST + st_;
        const int e0 = g * GCAP;
        const int e1 = g_cursor[g];
        const int cnt = e1 - e0;
        const uint4* p4 = (const uint4*)(g_pairs + e0);  // GCAP%4==0 -> aligned
        const int n4 = cnt >> 2;

        int i = tid;
        for (; i + 512 < n4; i += 1024) {
            uint4 q0 = p4[i];
            uint4 q1 = p4[i + 512];
            uint32_t p[8] = {q0.x, q0.y, q0.z, q0.w, q1.x, q1.y, q1.z, q1.w};
            float v[8];
            #pragma unroll
            for (int j = 0; j < 8; j++) v[j] = stage[p[j] & 16383u];
            #pragma unroll
            for (int j = 0; j < 8; j++) atomicAdd(&acc[p[j] >> 14], v[j]);
        }
        for (; i < n4; i += 512) {
            uint4 q = p4[i];
            uint32_t p[4] = {q.x, q.y, q.z, q.w};
            float v[4];
            #pragma unroll
            for (int j = 0; j < 4; j++) v[j] = stage[p[j] & 16383u];
            #pragma unroll
            for (int j = 0; j < 4; j++) atomicAdd(&acc[p[j] >> 14], v[j]);
        }
        for (int e = e0 + (n4 << 2) + tid; e < e1; e += 512) {
            uint32_t p = g_pairs[e];
            atomicAdd(&acc[p >> 14], stage[p & 16383u]);
        }
    }
    __syncthreads();

    // coalesced REDG writeback (2 replicas -> atomic)
    for (int i = tid; i < DT; i += 512) {
        int node = dbase + i;
        if (node < n) {
            float a = acc[i];
            if (a != 0.f) atomicAdd(&g_neigh[node], a);
        }
    }
}

// --- combine: out = h*ws + neigh*wn  (float4) ------------------------------
__global__ void combine_kernel(const float* __restrict__ h,
                               const float* __restrict__ w_self,
                               const float* __restrict__ w_neigh,
                               int hop,
                               float* __restrict__ out,
                               int n4) {
    int i = blockIdx.x * blockDim.x + threadIdx.x;
    if (i >= n4) return;
    float ws = __ldg(&w_self[hop]);
    float wn = __ldg(&w_neigh[hop]);
    float4 hv = ((const float4*)h)[i];
    float4 nv = ((const float4*)g_neigh)[i];
    float4 o;
    o.x = hv.x * ws + nv.x * wn;
    o.y = hv.y * ws + nv.y * wn;
    o.z = hv.z * ws + nv.z * wn;
    o.w = hv.w * ws + nv.w * wn;
    ((float4*)out)[i] = o;
}

extern "C" void kernel_launch(void* const* d_in, const int* in_sizes, int n_in,
                              void* d_out, int out_size) {
    const float* h_in    = (const float*)d_in[0];   // [N,1] f32
    const int*   src     = (const int*)d_in[1];     // [E] i32
    const int*   dst     = (const int*)d_in[2];     // [E] i32
    const float* w_self  = (const float*)d_in[3];   // [HOP,1,1]
    const float* w_neigh = (const float*)d_in[4];   // [HOP,1,1]
    float*       out     = (float*)d_out;

    const int n       = in_sizes[0];   // 1,000,000
    const int ne      = in_sizes[1];   // 32,000,000
    const int num_hop = in_sizes[3];   // 3

    float* gA; float* gB;
    cudaGetSymbolAddress((void**)&gA, g_hA);
    cudaGetSymbolAddress((void**)&gB, g_hB);

    const int binsort_smem = 3 * NGP * (int)sizeof(int) + CHUNK * (int)sizeof(uint32_t); // 224 KB
    cudaFuncSetAttribute(binsort_kernel,
                         cudaFuncAttributeMaxDynamicSharedMemorySize, binsort_smem);
    const int hop_smem = (DT + ST) * (int)sizeof(float);   // 112 KB -> 2 CTA/SM
    cudaFuncSetAttribute(hop_kernel,
                         cudaFuncAttributeMaxDynamicSharedMemorySize, hop_smem);

    const int n4 = n / 4;

    // launches: 0 init, 1 spacer, 2 binsort, 3 spacer, 4 zero, 5 hop (ncu -s5)
    init_cursor_kernel<<<(NG + 255) / 256, 256>>>();
    spacer_kernel<<<1, 32>>>();
    binsort_kernel<<<(ne + CHUNK - 1) / CHUNK, 512, binsort_smem>>>(src, dst, ne);
    spacer_kernel<<<1, 32>>>();

    const float* cur = h_in;
    for (int hop = 0; hop < num_hop; hop++) {
        float* o = (hop == num_hop - 1) ? out : ((hop & 1) ? gB : gA);
        zero_kernel<<<(n4 + 255) / 256, 256>>>(n4);
        hop_kernel<<<NDT * 2, 512, hop_smem>>>(cur, n);
        combine_kernel<<<(n4 + 255) / 256, 256>>>(cur, w_self, w_neigh, hop, o, n4);
        cur = o;
    }
}

// round 11
// speedup vs baseline: 1.0011x; 1.0011x over previous
#include <cuda_runtime.h>
#include <stdint.h>

// ---------------------------------------------------------------------------
// Graph-SAGE 3-hop, F=1.
// One-time: counting-sort edges into (dst-tile, src-tile) groups:
//   DT=12288 (82 dst tiles), ST=16384 (62 src tiles), 5084 groups.
// Per hop: zero g_neigh; hop kernel = persistent dst-tile blocks (2 replicas,
// grid 164): 48KB smem acc + 64KB smem src stage; per edge LDS + smem ATOMS;
// writeback = coalesced REDG (2M/hop, not 41M); then combine kernel.
// Packed edge = dst_local<<14 | src_local  (dst_local<12288, src_local<16384).
// ---------------------------------------------------------------------------

#define DT      12288
#define NDT     82                      // ceil(1e6/12288)
#define ST      16384
#define NST     62                      // ceil(1e6/16384)
#define NG      (NDT * NST)             // 5084
#define NGP     8192                    // pow2 >= NG (scan width)
#define GCAP    7936                    // mean 6442, std ~80 -> +18.7 sigma
#define CHUNK   32768                   // edges per binsort block
#define MAX_N   (NDT * DT)              // 1,007,616

__device__ uint32_t g_pairs[(size_t)NG * GCAP];   // ~161 MB scratch
__device__ int      g_cursor[NG];
__device__ float    g_neigh[MAX_N];
__device__ float    g_hA[MAX_N];
__device__ float    g_hB[MAX_N];
__device__ int      g_sink;

// --- init: cursor[g] = g*GCAP ----------------------------------------------
__global__ void init_cursor_kernel() {
    int g = blockIdx.x * blockDim.x + threadIdx.x;
    if (g < NG) g_cursor[g] = g * GCAP;
}

// --- spacer (launch-index alignment: ncu -s 5 lands on the hop kernel) -----
__global__ void spacer_kernel() {
    if (threadIdx.x == 0) g_sink = 1;
}

// --- binsort: smem counting sort of a 32K-edge chunk into 5084 groups ------
// dyn smem: cnt[NGP] | cur[NGP] | gbase[NGP] | buf[CHUNK]   (224 KB)
__global__ __launch_bounds__(512)
void binsort_kernel(const int* __restrict__ src,
                    const int* __restrict__ dst,
                    int ne) {
    extern __shared__ int sm[];
    int*      cnt   = sm;
    int*      cur   = sm + NGP;
    int*      gbase = sm + 2 * NGP;
    uint32_t* buf   = (uint32_t*)(sm + 3 * NGP);

    const int tid = threadIdx.x;
    const int lo = blockIdx.x * CHUNK;
    const int hi = min(ne, lo + CHUNK);

    #pragma unroll
    for (int k = 0; k < NGP / 512; k++) cnt[tid + 512 * k] = 0;
    __syncthreads();

    // Phase A: count groups (coalesced reads, spread smem atomics)
    for (int e = lo + tid; e < hi; e += 512) {
        int g = (dst[e] / DT) * NST + (src[e] >> 14);
        atomicAdd(&cnt[g], 1);
    }
    __syncthreads();

    // Phase B: Hillis-Steele inclusive scan over NGP (16 elems/thread)
    #pragma unroll
    for (int k = 0; k < NGP / 512; k++) cur[tid + 512 * k] = cnt[tid + 512 * k];
    __syncthreads();
    for (int off = 1; off < NGP; off <<= 1) {
        int a[NGP / 512];
        #pragma unroll
        for (int k = 0; k < NGP / 512; k++) {
            int i = tid + 512 * k;
            a[k] = (i >= off) ? cur[i - off] : 0;
        }
        __syncthreads();
        #pragma unroll
        for (int k = 0; k < NGP / 512; k++) cur[tid + 512 * k] += a[k];
        __syncthreads();
    }
    // exclusive start into cur; reserve global ranges
    {
        int s_[NGP / 512];
        #pragma unroll
        for (int k = 0; k < NGP / 512; k++) {
            int i = tid + 512 * k;
            s_[k] = cur[i] - cnt[i];
        }
        __syncthreads();
        #pragma unroll
        for (int k = 0; k < NGP / 512; k++) {
            int i = tid + 512 * k;
            cur[i]   = s_[k];
            gbase[i] = (i < NG && cnt[i]) ? atomicAdd(&g_cursor[i], cnt[i]) : 0;
        }
    }
    __syncthreads();

    // Phase C: scatter packed edges into smem buffer
    for (int e = lo + tid; e < hi; e += 512) {
        int d = dst[e], s = src[e];
        int dt_ = d / DT;
        int g = dt_ * NST + (s >> 14);
        int pos = atomicAdd(&cur[g], 1);
        buf[pos] = ((uint32_t)(d - dt_ * DT) << 14) | (uint32_t)(s & 16383);
    }
    __syncthreads();

    // Phase D: coalesced copy-out, one warp per group run (~6 words each)
    int warp = tid >> 5, lane = tid & 31;
    for (int g = warp; g < NG; g += 16) {
        int c = cnt[g];
        if (!c) continue;
        int sb = cur[g] - c;          // cur is now exclusive start + cnt
        int gb = gbase[g];
        for (int j = lane; j < c; j += 32)
            g_pairs[gb + j] = buf[sb + j];
    }
}

// --- zero the global neighbor accumulator ----------------------------------
__global__ void zero_kernel(int n4) {
    int i = blockIdx.x * blockDim.x + threadIdx.x;
    if (i < n4) ((float4*)g_neigh)[i] = make_float4(0.f, 0.f, 0.f, 0.f);
}

// --- hop: persistent dst-tile block (2 replicas), loops over src-tiles -----
__global__ __launch_bounds__(512)
void hop_kernel(const float* __restrict__ h, int n) {
    extern __shared__ float fsm[];
    float* acc   = fsm;          // DT floats (48 KB)
    float* stage = fsm + DT;     // ST floats (64 KB)

    const int bid  = blockIdx.x;
    const int dt_  = bid >> 1;
    const int rep  = bid & 1;
    const int tid  = threadIdx.x;
    const int dbase = dt_ * DT;

    for (int i = tid; i < DT; i += 512) acc[i] = 0.f;

    for (int st_ = rep; st_ < NST; st_ += 2) {
        const int sbase = st_ << 14;
        __syncthreads();   // prior-iter stage readers done; also orders acc zero
        // stage h[src tile] into smem
        if (sbase + ST <= n) {
            const float4* h4 = (const float4*)(h + sbase);
            for (int i = tid; i < ST / 4; i += 512)
                ((float4*)stage)[i] = h4[i];
        } else {
            for (int i = tid; i < ST; i += 512) {
                int node = sbase + i;
                stage[i] = (node < n) ? h[node] : 0.f;
            }
        }
        __syncthreads();

        const int g  = dt_ * NST + st_;
        const int e0 = g * GCAP;
        const int e1 = g_cursor[g];
        const int cnt = e1 - e0;
        const uint4* p4 = (const uint4*)(g_pairs + e0);  // GCAP%4==0 -> aligned
        const int n4 = cnt >> 2;

        int i = tid;
        for (; i + 512 < n4; i += 1024) {
            uint4 q0 = p4[i];
            uint4 q1 = p4[i + 512];
            uint32_t p[8] = {q0.x, q0.y, q0.z, q0.w, q1.x, q1.y, q1.z, q1.w};
            float v[8];
            #pragma unroll
            for (int j = 0; j < 8; j++) v[j] = stage[p[j] & 16383u];
            #pragma unroll
            for (int j = 0; j < 8; j++) atomicAdd(&acc[p[j] >> 14], v[j]);
        }
        for (; i < n4; i += 512) {
            uint4 q = p4[i];
            uint32_t p[4] = {q.x, q.y, q.z, q.w};
            float v[4];
            #pragma unroll
            for (int j = 0; j < 4; j++) v[j] = stage[p[j] & 16383u];
            #pragma unroll
            for (int j = 0; j < 4; j++) atomicAdd(&acc[p[j] >> 14], v[j]);
        }
        for (int e = e0 + (n4 << 2) + tid; e < e1; e += 512) {
            uint32_t p = g_pairs[e];
            atomicAdd(&acc[p >> 14], stage[p & 16383u]);
        }
    }
    __syncthreads();

    // coalesced REDG writeback (2 replicas -> atomic)
    for (int i = tid; i < DT; i += 512) {
        int node = dbase + i;
        if (node < n) {
            float a = acc[i];
            if (a != 0.f) atomicAdd(&g_neigh[node], a);
        }
    }
}

// --- combine: out = h*ws + neigh*wn  (float4) ------------------------------
__global__ void combine_kernel(const float* __restrict__ h,
                               const float* __restrict__ w_self,
                               const float* __restrict__ w_neigh,
                               int hop,
                               float* __restrict__ out,
                               int n4) {
    int i = blockIdx.x * blockDim.x + threadIdx.x;
    if (i >= n4) return;
    float ws = __ldg(&w_self[hop]);
    float wn = __ldg(&w_neigh[hop]);
    float4 hv = ((const float4*)h)[i];
    float4 nv = ((const float4*)g_neigh)[i];
    float4 o;
    o.x = hv.x * ws + nv.x * wn;
    o.y = hv.y * ws + nv.y * wn;
    o.z = hv.z * ws + nv.z * wn;
    o.w = hv.w * ws + nv.w * wn;
    ((float4*)out)[i] = o;
}

extern "C" void kernel_launch(void* const* d_in, const int* in_sizes, int n_in,
                              void* d_out, int out_size) {
    const float* h_in    = (const float*)d_in[0];   // [N,1] f32
    const int*   src     = (const int*)d_in[1];     // [E] i32
    const int*   dst     = (const int*)d_in[2];     // [E] i32
    const float* w_self  = (const float*)d_in[3];   // [HOP,1,1]
    const float* w_neigh = (const float*)d_in[4];   // [HOP,1,1]
    float*       out     = (float*)d_out;

    const int n       = in_sizes[0];   // 1,000,000
    const int ne      = in_sizes[1];   // 32,000,000
    const int num_hop = in_sizes[3];   // 3

    float* gA; float* gB;
    cudaGetSymbolAddress((void**)&gA, g_hA);
    cudaGetSymbolAddress((void**)&gB, g_hB);

    const int binsort_smem = 3 * NGP * (int)sizeof(int) + CHUNK * (int)sizeof(uint32_t); // 224 KB
    cudaFuncSetAttribute(binsort_kernel,
                         cudaFuncAttributeMaxDynamicSharedMemorySize, binsort_smem);
    const int hop_smem = (DT + ST) * (int)sizeof(float);   // 112 KB -> 2 CTA/SM
    cudaFuncSetAttribute(hop_kernel,
                         cudaFuncAttributeMaxDynamicSharedMemorySize, hop_smem);

    const int n4 = n / 4;

    // launches: 0 init, 1 spacer, 2 binsort, 3 spacer, 4 zero, 5 hop (ncu -s5)
    init_cursor_kernel<<<(NG + 255) / 256, 256>>>();
    spacer_kernel<<<1, 32>>>();
    binsort_kernel<<<(ne + CHUNK - 1) / CHUNK, 512, binsort_smem>>>(src, dst, ne);
    spacer_kernel<<<1, 32>>>();

    const float* cur = h_in;
    for (int hop = 0; hop < num_hop; hop++) {
        float* o = (hop == num_hop - 1) ? out : ((hop & 1) ? gB : gA);
        zero_kernel<<<(n4 + 255) / 256, 256>>>(n4);
        hop_kernel<<<NDT * 2, 512, hop_smem>>>(cur, n);
        combine_kernel<<<(n4 + 255) / 256, 256>>>(cur, w_self, w_neigh, hop, o, n4);
        cur = o;
    }
}